// round 1
// baseline (speedup 1.0000x reference)
#include <cuda_runtime.h>
#include <math.h>

#define NN 40000
#define EE 640000
#define D  128
#define DOUT 40
#define HBITS 21
#define HSIZE (1 << HBITS)
#define HMASK (HSIZE - 1)

// ---------------- scratch (static device globals; no allocation) ------------
__device__ int   g_degE[NN];
__device__ float g_dis[NN];
__device__ int   g_rowptr[NN + 1];
__device__ int   g_cursor[NN];
__device__ int   g_csrc[EE];
__device__ float g_cnorm[EE];
__device__ float g_h [NN * D];
__device__ float g_y [NN * D];
__device__ float g_h3[NN * DOUT];
__device__ int   g_hk[HSIZE];
__device__ int   g_hc[HSIZE];
__device__ unsigned int g_reg;

// ---------------- init: reset per-call state --------------------------------
__global__ void k_init() {
    int i = blockIdx.x * blockDim.x + threadIdx.x;
    int stride = gridDim.x * blockDim.x;
    for (int j = i; j < HSIZE; j += stride) { g_hk[j] = -1; g_hc[j] = 0; }
    for (int j = i; j < NN; j += stride) g_degE[j] = 0;
    if (i == 0) g_reg = 0u;
}

// ---------------- degree histogram ------------------------------------------
__global__ void k_deg(const int* __restrict__ dst, int E) {
    int e = blockIdx.x * blockDim.x + threadIdx.x;
    if (e < E) atomicAdd(&g_degE[dst[e]], 1);
}

// ---------------- 1-block exclusive scan + dis + cursor ---------------------
__global__ void k_scan(int n, int E) {
    __shared__ int sm[1024];
    int t = threadIdx.x;
    int chunk = (n + 1023) / 1024;
    int lo = t * chunk;
    int hi = lo + chunk; if (hi > n) hi = n;
    int s = 0;
    for (int i = lo; i < hi; i++) s += g_degE[i];
    sm[t] = s;
    __syncthreads();
    // Hillis-Steele inclusive scan
    for (int off = 1; off < 1024; off <<= 1) {
        int v = (t >= off) ? sm[t - off] : 0;
        __syncthreads();
        sm[t] += v;
        __syncthreads();
    }
    int base = sm[t] - s;  // exclusive prefix
    for (int i = lo; i < hi; i++) {
        int d = g_degE[i];
        g_rowptr[i] = base;
        g_cursor[i] = base;
        g_dis[i] = rsqrtf((float)(d + 1));  // self-loop included in degree
        base += d;
    }
    if (t == 1023) g_rowptr[n] = E;
}

// ---------------- scatter edges into CSR (by dst) ----------------------------
__global__ void k_scatter(const int* __restrict__ src, const int* __restrict__ dst, int E) {
    int e = blockIdx.x * blockDim.x + threadIdx.x;
    if (e >= E) return;
    int s = src[e], d = dst[e];
    int pos = atomicAdd(&g_cursor[d], 1);
    g_csrc[pos]  = s;
    g_cnorm[pos] = g_dis[s] * g_dis[d];
}

// ---------------- hash table for reg_loss -----------------------------------
__device__ __forceinline__ unsigned int hmix(unsigned int k) {
    k *= 2654435761u;
    k ^= k >> 15;
    return k;
}

__global__ void k_hins(const int* __restrict__ src, const int* __restrict__ dst, int E, int n) {
    int e = blockIdx.x * blockDim.x + threadIdx.x;
    if (e >= E) return;
    unsigned int key = (unsigned int)src[e] * (unsigned int)n + (unsigned int)dst[e];
    unsigned int slot = hmix(key) & HMASK;
    while (true) {
        int old = atomicCAS(&g_hk[slot], -1, (int)key);
        if (old == -1 || old == (int)key) { atomicAdd(&g_hc[slot], 1); break; }
        slot = (slot + 1) & HMASK;
    }
}

__global__ void k_hlook(const int* __restrict__ src, const int* __restrict__ dst, int E, int n) {
    int e = blockIdx.x * blockDim.x + threadIdx.x;
    if (e >= E) return;
    unsigned int rkey = (unsigned int)dst[e] * (unsigned int)n + (unsigned int)src[e];
    unsigned int slot = hmix(rkey) & HMASK;
    int c = 0;
    while (true) {
        int k = g_hk[slot];
        if (k == -1) break;
        if (k == (int)rkey) { c = g_hc[slot]; break; }
        slot = (slot + 1) & HMASK;
    }
    if (c) atomicAdd(&g_reg, (unsigned int)c);
}

__global__ void k_wreg(float* out, int idx) {
    if (blockIdx.x == 0 && threadIdx.x == 0) out[idx] = (float)g_reg;
}

// ---------------- SGEMM: [M,128] @ [128,128], W resident in SMEM ------------
// warp computes 4 rows x 128 cols; lane owns 4 contiguous cols (float4 LDS).
__global__ void k_gemm128(const float* __restrict__ X, const float* __restrict__ W,
                          float* __restrict__ H, int M) {
    extern __shared__ float Ws[];  // 128*128 floats = 64 KB
    for (int i = threadIdx.x; i < D * D; i += blockDim.x) Ws[i] = W[i];
    __syncthreads();

    const int lane = threadIdx.x & 31;
    const int wid  = threadIdx.x >> 5;
    const int gw   = blockIdx.x * (blockDim.x >> 5) + wid;
    const int nw   = (blockDim.x >> 5) * gridDim.x;

    for (int r0 = gw * 4; r0 < M; r0 += nw * 4) {
        float xr[4][4];
#pragma unroll
        for (int r = 0; r < 4; r++) {
            const float* xp = X + (r0 + r) * D;
#pragma unroll
            for (int j = 0; j < 4; j++) xr[r][j] = xp[lane + 32 * j];
        }
        float4 acc[4];
#pragma unroll
        for (int r = 0; r < 4; r++) acc[r] = make_float4(0.f, 0.f, 0.f, 0.f);

#pragma unroll
        for (int j = 0; j < 4; j++) {
#pragma unroll 8
            for (int l = 0; l < 32; l++) {
                float4 wv = *(const float4*)&Ws[(j * 32 + l) * D + lane * 4];
#pragma unroll
                for (int r = 0; r < 4; r++) {
                    float xk = __shfl_sync(0xffffffffu, xr[r][j], l);
                    acc[r].x += xk * wv.x;
                    acc[r].y += xk * wv.y;
                    acc[r].z += xk * wv.z;
                    acc[r].w += xk * wv.w;
                }
            }
        }
#pragma unroll
        for (int r = 0; r < 4; r++)
            *(float4*)&H[(r0 + r) * D + lane * 4] = acc[r];
    }
}

// ---------------- SGEMM: [M,128] @ [128,40] ----------------------------------
__global__ void k_gemm40(const float* __restrict__ X, const float* __restrict__ W,
                         float* __restrict__ H3, int M) {
    __shared__ float Ws[D * DOUT + 32];
    for (int i = threadIdx.x; i < D * DOUT + 32; i += blockDim.x)
        Ws[i] = (i < D * DOUT) ? W[i] : 0.f;
    __syncthreads();

    const int lane = threadIdx.x & 31;
    const int wid  = threadIdx.x >> 5;
    const int gw   = blockIdx.x * (blockDim.x >> 5) + wid;
    const int nw   = (blockDim.x >> 5) * gridDim.x;

    for (int r0 = gw * 4; r0 < M; r0 += nw * 4) {
        float xr[4][4];
#pragma unroll
        for (int r = 0; r < 4; r++) {
            const float* xp = X + (r0 + r) * D;
#pragma unroll
            for (int j = 0; j < 4; j++) xr[r][j] = xp[lane + 32 * j];
        }
        float a0[4] = {0.f, 0.f, 0.f, 0.f};
        float a1[4] = {0.f, 0.f, 0.f, 0.f};
#pragma unroll
        for (int j = 0; j < 4; j++) {
#pragma unroll 8
            for (int l = 0; l < 32; l++) {
                int k = j * 32 + l;
                float w0 = Ws[k * DOUT + lane];
                float w1 = Ws[k * DOUT + 32 + lane];  // pad-safe; lanes>=8 unused
#pragma unroll
                for (int r = 0; r < 4; r++) {
                    float xk = __shfl_sync(0xffffffffu, xr[r][j], l);
                    a0[r] += xk * w0;
                    a1[r] += xk * w1;
                }
            }
        }
#pragma unroll
        for (int r = 0; r < 4; r++) {
            H3[(r0 + r) * DOUT + lane] = a0[r];
            if (lane < 8) H3[(r0 + r) * DOUT + 32 + lane] = a1[r];
        }
    }
}

// ---------------- aggregation (128-d) + bias + ReLU, warp per node ----------
__global__ void k_agg128(const float* __restrict__ Hh, const float* __restrict__ b,
                         float* __restrict__ Y, int n) {
    const int lane = threadIdx.x & 31;
    const int i = blockIdx.x * (blockDim.x >> 5) + (threadIdx.x >> 5);
    if (i >= n) return;

    const float4* H4 = (const float4*)Hh;
    float d = g_dis[i];
    float d2 = d * d;
    float4 acc = H4[i * 32 + lane];
    acc.x *= d2; acc.y *= d2; acc.z *= d2; acc.w *= d2;

    int p  = g_rowptr[i];
    int pe = g_rowptr[i + 1];
    for (; p + 1 < pe; p += 2) {
        int   s0 = g_csrc[p],   s1 = g_csrc[p + 1];
        float w0 = g_cnorm[p],  w1 = g_cnorm[p + 1];
        float4 v0 = H4[s0 * 32 + lane];
        float4 v1 = H4[s1 * 32 + lane];
        acc.x += w0 * v0.x + w1 * v1.x;
        acc.y += w0 * v0.y + w1 * v1.y;
        acc.z += w0 * v0.z + w1 * v1.z;
        acc.w += w0 * v0.w + w1 * v1.w;
    }
    if (p < pe) {
        int s = g_csrc[p];
        float w = g_cnorm[p];
        float4 v = H4[s * 32 + lane];
        acc.x += w * v.x; acc.y += w * v.y; acc.z += w * v.z; acc.w += w * v.w;
    }

    float4 bb = *(const float4*)&b[lane * 4];
    acc.x = fmaxf(acc.x + bb.x, 0.f);
    acc.y = fmaxf(acc.y + bb.y, 0.f);
    acc.z = fmaxf(acc.z + bb.z, 0.f);
    acc.w = fmaxf(acc.w + bb.w, 0.f);
    ((float4*)Y)[i * 32 + lane] = acc;
}

// ---------------- aggregation (40-d) + bias + log_softmax -------------------
__global__ void k_agg40(const float* __restrict__ H3, const float* __restrict__ b,
                        float* __restrict__ out, int n) {
    const int lane = threadIdx.x & 31;
    const int i = blockIdx.x * (blockDim.x >> 5) + (threadIdx.x >> 5);
    if (i >= n) return;

    float d = g_dis[i];
    float d2 = d * d;
    float a0 = d2 * H3[i * DOUT + lane];
    float a1 = (lane < 8) ? d2 * H3[i * DOUT + 32 + lane] : 0.f;

    int p  = g_rowptr[i];
    int pe = g_rowptr[i + 1];
    for (; p < pe; p++) {
        int s = g_csrc[p];
        float w = g_cnorm[p];
        a0 += w * H3[s * DOUT + lane];
        if (lane < 8) a1 += w * H3[s * DOUT + 32 + lane];
    }

    float v0 = a0 + b[lane];
    float v1 = (lane < 8) ? (a1 + b[32 + lane]) : -INFINITY;

    float m = fmaxf(v0, v1);
#pragma unroll
    for (int o = 16; o; o >>= 1) m = fmaxf(m, __shfl_xor_sync(0xffffffffu, m, o));
    float se = expf(v0 - m) + ((lane < 8) ? expf(v1 - m) : 0.f);
#pragma unroll
    for (int o = 16; o; o >>= 1) se += __shfl_xor_sync(0xffffffffu, se, o);
    float ls = m + logf(se);

    out[i * DOUT + lane] = v0 - ls;
    if (lane < 8) out[i * DOUT + 32 + lane] = v1 - ls;
}

// ---------------- launch ------------------------------------------------------
extern "C" void kernel_launch(void* const* d_in, const int* in_sizes, int n_in,
                              void* d_out, int out_size) {
    const float* x  = (const float*)d_in[0];
    const int*   ei = (const int*)d_in[1];
    const float* W1 = (const float*)d_in[2];
    const float* b1 = (const float*)d_in[3];
    const float* W2 = (const float*)d_in[4];
    const float* b2 = (const float*)d_in[5];
    const float* W3 = (const float*)d_in[6];
    const float* b3 = (const float*)d_in[7];
    float* out = (float*)d_out;

    const int n = in_sizes[0] / D;      // 40000
    const int E = in_sizes[1] / 2;      // 640000
    const int* src = ei;
    const int* dst = ei + E;

    cudaFuncSetAttribute(k_gemm128, cudaFuncAttributeMaxDynamicSharedMemorySize, 65536);

    const int TB = 256;
    const int eblocks = (E + TB - 1) / TB;
    const int wblocks = (n + (TB / 32) - 1) / (TB / 32);  // warp per node

    // graph structure (recomputed every call; deterministic)
    k_init<<<4096, TB>>>();
    k_deg<<<eblocks, TB>>>(dst, E);
    k_scan<<<1, 1024>>>(n, E);
    k_scatter<<<eblocks, TB>>>(src, dst, E);

    // reg_loss (independent of GCN layers)
    k_hins<<<eblocks, TB>>>(src, dst, E, n);
    k_hlook<<<eblocks, TB>>>(src, dst, E, n);
    k_wreg<<<1, 32>>>(out, out_size - 1);

    // layer 1
    k_gemm128<<<444, TB, 65536>>>(x, W1, g_h, n);
    k_agg128<<<wblocks, TB>>>(g_h, b1, g_y, n);
    // layer 2
    k_gemm128<<<444, TB, 65536>>>(g_y, W2, g_h, n);
    k_agg128<<<wblocks, TB>>>(g_h, b2, g_y, n);
    // layer 3 + log_softmax
    k_gemm40<<<444, TB>>>(g_y, W3, g_h3, n);
    k_agg40<<<wblocks, TB>>>(g_h3, b3, out, n);
}